// round 17
// baseline (speedup 1.0000x reference)
#include <cuda_runtime.h>
#include <cuda_fp16.h>
#include <math.h>
#include <stdint.h>

typedef __half HF;

#define NB   4096
#define DIN  1024
#define DOUT 1024
#define TAU  2.5e-3f
#define MAXFIX 131072

// ---------------- scratch (__device__ globals; allocation-free rule) ----------------
__device__ HF g_xh [NB * DIN];
__device__ HF g_hph[NB * DOUT];
__device__ HF g_acth[NB * 2*DOUT];    // activated (fp16)
__device__ HF g_hrh[NB * DOUT];       // h_prev*r  (fp16)
__device__ HF g_w1 [2048*2048];       // W_in^T  [N=2048][K=2048] (fp16 truncated)
__device__ HF g_wzr[2048*3072];       // [Wz|Wr]^T [N=2048][K=3072]
__device__ HF g_wn [1024*3072];       // W_n^T   [N=1024][K=3072]
__device__ float g_z[NB * DOUT];
__device__ int g_fix[MAXFIX];
__device__ int g_cnt;

// ---------------- PTX helpers (arch-generic) ----------------
__device__ __forceinline__ void cp16(uint32_t s, const void* g) {
    asm volatile("cp.async.cg.shared.global [%0], [%1], 16;" :: "r"(s), "l"(g));
}
__device__ __forceinline__ void cp_commit() { asm volatile("cp.async.commit_group;"); }
template<int N> __device__ __forceinline__ void cp_wait() {
    asm volatile("cp.async.wait_group %0;" :: "n"(N) : "memory");
}
__device__ __forceinline__ void ldsm4(uint32_t* r, uint32_t addr) {
    asm volatile("ldmatrix.sync.aligned.m8n8.x4.shared.b16 {%0,%1,%2,%3}, [%4];"
                 : "=r"(r[0]), "=r"(r[1]), "=r"(r[2]), "=r"(r[3]) : "r"(addr));
}
__device__ __forceinline__ void mma16816(float* d, const uint32_t* a, uint32_t b0, uint32_t b1) {
    asm volatile(
        "mma.sync.aligned.m16n8k16.row.col.f32.f16.f16.f32 "
        "{%0,%1,%2,%3}, {%4,%5,%6,%7}, {%8,%9}, {%0,%1,%2,%3};"
        : "+f"(d[0]), "+f"(d[1]), "+f"(d[2]), "+f"(d[3])
        : "r"(a[0]), "r"(a[1]), "r"(a[2]), "r"(a[3]), "r"(b0), "r"(b1));
}
// 64B-row tile: chunk swizzle (conflict-free ldmatrix phases)
__device__ __forceinline__ uint32_t tswz(uint32_t row, uint32_t chunk) {
    return row * 64u + ((chunk ^ ((row >> 1) & 3u)) * 16u);
}

// ---------------- preprocess ----------------
__global__ void zero_cnt_kernel() { g_cnt = 0; }

__global__ void trunc_rows(const float* __restrict__ in, HF* __restrict__ oh, int n4) {
    for (int i = blockIdx.x * blockDim.x + threadIdx.x; i < n4; i += gridDim.x * blockDim.x) {
        float4 v = ((const float4*)in)[i];
        __half2* ph = (__half2*)(oh + (size_t)i * 4);
        ph[0] = __halves2half2(__float2half(v.x), __float2half(v.y));
        ph[1] = __halves2half2(__float2half(v.z), __float2half(v.w));
    }
}

// W [K x N] fp32 -> fp16-truncated transpose rows [n_off + n][k], ldT = K
__global__ void transpose_h(const float* __restrict__ W, int K, int N,
                            HF* __restrict__ Th, int n_off, int ldT) {
    __shared__ float t[32][33];
    int k0 = blockIdx.y * 32, n0 = blockIdx.x * 32;
    int tx = threadIdx.x, ty = threadIdx.y;
#pragma unroll
    for (int i = 0; i < 32; i += 8)
        t[ty + i][tx] = W[(size_t)(k0 + ty + i) * N + n0 + tx];
    __syncthreads();
#pragma unroll
    for (int i = 0; i < 32; i += 8) {
        size_t o = (size_t)(n_off + n0 + ty + i) * ldT + k0 + tx;
        Th[o] = __float2half(t[tx][ty + i]);
    }
}

// ---------------- HMMA GEMM: BM=128 BN=128 BK=32, single-pass fp16, 4-stage ----------------
// per stage: 2 tiles (A, B), each 128 rows x 64B (swizzled) = 8KB
constexpr uint32_t T_B = 8192;
constexpr uint32_t STAGE = 16384;
constexpr int NSTAGE = 4;
constexpr int SMEM_BYTES = NSTAGE * (int)STAGE;   // 64KB (2 CTAs/SM: 128KB of 228KB)

template<int MODE>
__global__ __launch_bounds__(256, 2)
void mma_gemm(const HF* __restrict__ A0, int ldA0, int K0,
              const HF* __restrict__ A1, int ldA1,
              const HF* __restrict__ Bt, int Ktot,
              const float* __restrict__ bias, const float* __restrict__ q0,
              const float* __restrict__ q1, const float* __restrict__ q2,
              float* __restrict__ of, HF* __restrict__ oh)
{
    extern __shared__ char smv[];
    const int tid = threadIdx.x, wid = tid >> 5, lane = tid & 31;
    const int bm = blockIdx.y * 128, bn = blockIdx.x * 128;
    const int wm = (wid >> 1) * 32, wn = (wid & 1) * 64;
    const uint32_t sb = (uint32_t)__cvta_generic_to_shared(smv);

    const int r_ld = tid >> 1;           // 0..127
    const int c_ld = (tid & 1) * 2;      // 16B-chunk 0 or 2

    const int KT = Ktot >> 5;

    auto issue = [&](int kt) {
        if (kt >= KT) { cp_commit(); return; }   // empty group keeps wait_group accounting
        const uint32_t base = sb + (uint32_t)(kt % NSTAGE) * STAGE;
        const int kb = kt * 32;
        const HF* ah; int lda, kk;
        if (kb < K0) { ah = A0; lda = ldA0; kk = kb; }
        else         { ah = A1; lda = ldA1; kk = kb - K0; }
        const size_t ga = (size_t)(bm + r_ld) * lda + kk + c_ld * 8;
        const size_t gb = (size_t)(bn + r_ld) * Ktot + kb + c_ld * 8;
        const uint32_t s0 = tswz(r_ld, c_ld), s1 = tswz(r_ld, c_ld + 1);
        cp16(base + s0,       ah + ga); cp16(base + s1,       ah + ga + 8);
        cp16(base + T_B + s0, Bt + gb); cp16(base + T_B + s1, Bt + gb + 8);
        cp_commit();
    };

    float acc[16][4];
#pragma unroll
    for (int i = 0; i < 16; i++)
#pragma unroll
        for (int j = 0; j < 4; j++) acc[i][j] = 0.f;

    issue(0); issue(1); issue(2);
    for (int kt = 0; kt < KT; ++kt) {
        cp_wait<2>();
        __syncthreads();          // stage kt ready; stage kt-1 fully consumed by all warps
        issue(kt + 3);            // refill stage (kt+3)%4 == (kt-1)%4
        const uint32_t base = sb + (uint32_t)(kt % NSTAGE) * STAGE;
#pragma unroll
        for (int ks = 0; ks < 2; ++ks) {
            uint32_t ahr[2][4];
#pragma unroll
            for (int i = 0; i < 2; i++) {
                const uint32_t row = (uint32_t)(wm + i * 16 + (lane & 7) + ((lane >> 3) & 1) * 8);
                ldsm4(ahr[i], base + tswz(row, (uint32_t)(ks * 2 + (lane >> 4))));
            }
#pragma unroll
            for (int jj = 0; jj < 4; jj++) {
                const uint32_t nrow = (uint32_t)(wn + jj * 16 + (lane & 7) + (lane >> 4) * 8);
                uint32_t bh[4];
                ldsm4(bh, base + T_B + tswz(nrow, (uint32_t)(ks * 2 + ((lane >> 3) & 1))));
#pragma unroll
                for (int h = 0; h < 2; h++)
#pragma unroll
                    for (int i = 0; i < 2; i++)
                        mma16816(acc[i * 8 + 2 * jj + h], ahr[i], bh[2*h], bh[2*h+1]);
            }
        }
    }
    cp_wait<0>();

    // ---- epilogue (element pairs: n, n+1) ----
#pragma unroll
    for (int i = 0; i < 2; i++) {
#pragma unroll
        for (int nf = 0; nf < 8; nf++) {
#pragma unroll
            for (int hh = 0; hh < 2; hh++) {
                const int m = bm + wm + i * 16 + (lane >> 2) + hh * 8;
                const int n = bn + wn + nf * 8 + (lane & 3) * 2;
                float v0 = acc[i * 8 + nf][hh * 2 + 0];
                float v1 = acc[i * 8 + nf][hh * 2 + 1];
                if (MODE == 1) {
                    const size_t o = (size_t)m * 2048 + n;
                    float c0 = v0 + bias[n]     + q0[o];
                    float c1 = v1 + bias[n + 1] + q0[o + 1];
                    bool s0 = c0 > q1[n], s1 = c1 > q1[n + 1];
                    float2 pv = { s0 ? 0.f : c0 * q2[n], s1 ? 0.f : c1 * q2[n + 1] };
                    *(float2*)(of + o) = pv;
                    float a0 = s0 ? c0 : 0.f, a1 = s1 ? c1 : 0.f;
                    *(__half2*)(oh + o) = __halves2half2(__float2half(a0), __float2half(a1));
                    if (fabsf(c0 - q1[n]) < TAU) {
                        int ix = atomicAdd(&g_cnt, 1);
                        if (ix < MAXFIX) g_fix[ix] = (int)(m * 2048 + n);
                    }
                    if (fabsf(c1 - q1[n + 1]) < TAU) {
                        int ix = atomicAdd(&g_cnt, 1);
                        if (ix < MAXFIX) g_fix[ix] = (int)(m * 2048 + n + 1);
                    }
                } else if (MODE == 2) {
                    if (n < 1024) {
                        const size_t o = (size_t)m * 1024 + n;
                        float s0 = 1.f / (1.f + expf(-(v0 + bias[n])));
                        float s1 = 1.f / (1.f + expf(-(v1 + bias[n + 1])));
                        *(float2*)(of + o) = make_float2(s0, s1);
                    } else {
                        const int nn = n - 1024;
                        const size_t o = (size_t)m * 1024 + nn;
                        float s0 = 1.f / (1.f + expf(-(v0 + q0[nn])));
                        float s1 = 1.f / (1.f + expf(-(v1 + q0[nn + 1])));
                        float hr0 = q1[o] * s0, hr1 = q1[o + 1] * s1;
                        *(__half2*)(oh + o) = __halves2half2(__float2half(hr0), __float2half(hr1));
                    }
                } else {
                    const size_t o = (size_t)m * 1024 + n;
                    float t0 = tanhf(v0 + bias[n]);
                    float t1 = tanhf(v1 + bias[n + 1]);
                    float z0 = q0[o], z1 = q0[o + 1];
                    float hp0 = q1[o], hp1 = q1[o + 1];
                    *(float2*)(of + o) = make_float2((1.f - z0) * hp0 + z0 * t0,
                                                     (1.f - z1) * hp1 + z1 * t1);
                }
            }
        }
    }
}

// ---------------- exact (fp64) fixup of near-threshold spikes ----------------
__global__ void fixup(const float* __restrict__ x, const float* __restrict__ h_prev,
                      const float* __restrict__ W_in, const float* __restrict__ b_in,
                      const float* __restrict__ pot_prev, const float* __restrict__ tresh,
                      const float* __restrict__ decay,
                      float* __restrict__ pot_out, HF* __restrict__ act_hi)
{
    int w = (blockIdx.x * blockDim.x + threadIdx.x) >> 5;
    int l = threadIdx.x & 31;
    int nw = (gridDim.x * blockDim.x) >> 5;
    int cnt = g_cnt; if (cnt > MAXFIX) cnt = MAXFIX;
    for (; w < cnt; w += nw) {
        int o = g_fix[w];
        int m = o >> 11, n = o & 2047;
        double s = 0.0;
        for (int k = l; k < 2048; k += 32) {
            float a = (k < 1024) ? x[(size_t)m * 1024 + k] : h_prev[(size_t)m * 1024 + k - 1024];
            s += (double)a * (double)W_in[(size_t)k * 2048 + n];
        }
#pragma unroll
        for (int d = 16; d; d >>= 1) s += __shfl_xor_sync(0xFFFFFFFFu, s, d);
        if (l == 0) {
            float cc = (float)s + b_in[n] + pot_prev[(size_t)m * 2048 + n];
            bool sp = cc > tresh[n];
            pot_out[(size_t)m * 2048 + n] = sp ? 0.f : cc * decay[n];
            act_hi[(size_t)m * 2048 + n] = __float2half(sp ? cc : 0.f);
        }
    }
}

// ---------------- launch ----------------
extern "C" void kernel_launch(void* const* d_in, const int* in_sizes, int n_in,
                              void* d_out, int out_size)
{
    const float* x        = (const float*)d_in[0];
    const float* h_prev   = (const float*)d_in[1];
    const float* pot_prev = (const float*)d_in[2];
    const float* W_in     = (const float*)d_in[3];
    const float* b_in     = (const float*)d_in[4];
    const float* tresh    = (const float*)d_in[5];
    const float* decay    = (const float*)d_in[6];
    const float* W_z      = (const float*)d_in[7];
    const float* b_z      = (const float*)d_in[8];
    const float* W_r      = (const float*)d_in[9];
    const float* b_r      = (const float*)d_in[10];
    const float* W_n      = (const float*)d_in[11];
    const float* b_n      = (const float*)d_in[12];

    float* h_out   = (float*)d_out;                 // [4096,1024]
    float* pot_out = h_out + (size_t)NB * DOUT;     // [4096,2048]

    HF *xh, *hph, *acth, *hrh, *w1, *wzr, *wn;
    float* zbuf;
    cudaGetSymbolAddress((void**)&xh, g_xh);
    cudaGetSymbolAddress((void**)&hph, g_hph);
    cudaGetSymbolAddress((void**)&acth, g_acth);
    cudaGetSymbolAddress((void**)&hrh, g_hrh);
    cudaGetSymbolAddress((void**)&w1, g_w1);
    cudaGetSymbolAddress((void**)&wzr, g_wzr);
    cudaGetSymbolAddress((void**)&wn, g_wn);
    cudaGetSymbolAddress((void**)&zbuf, g_z);

    cudaFuncSetAttribute(mma_gemm<1>, cudaFuncAttributeMaxDynamicSharedMemorySize, SMEM_BYTES);
    cudaFuncSetAttribute(mma_gemm<2>, cudaFuncAttributeMaxDynamicSharedMemorySize, SMEM_BYTES);
    cudaFuncSetAttribute(mma_gemm<3>, cudaFuncAttributeMaxDynamicSharedMemorySize, SMEM_BYTES);

    // Launch order arranged so graph-launch index 5 (ncu -s 5 -c 1) is gemm1.
    zero_cnt_kernel<<<1, 1>>>();                                                   // 0
    trunc_rows<<<2048, 256>>>(x, xh, NB * DIN / 4);                                // 1
    trunc_rows<<<2048, 256>>>(h_prev, hph, NB * DOUT / 4);                         // 2
    transpose_h<<<dim3(64, 64), dim3(32, 8)>>>(W_in, 2048, 2048, w1, 0, 2048);     // 3
    transpose_h<<<dim3(32, 96), dim3(32, 8)>>>(W_z, 3072, 1024, wzr, 0, 3072);     // 4

    // 5) pot_tmp = [x|h_prev]@W_in + b + pot_prev ; spike -> activated, pot_next
    mma_gemm<1><<<dim3(16, 32), 256, SMEM_BYTES>>>(
        xh, DIN, DIN, hph, DOUT,
        w1, 2048,
        b_in, pot_prev, tresh, decay,
        pot_out, acth);

    fixup<<<64, 256>>>(x, h_prev, W_in, b_in, pot_prev, tresh, decay, pot_out, acth);  // 6
    transpose_h<<<dim3(32, 96), dim3(32, 8)>>>(W_r, 3072, 1024, wzr, 1024, 3072);  // 7
    transpose_h<<<dim3(32, 96), dim3(32, 8)>>>(W_n, 3072, 1024, wn, 0, 3072);      // 8

    // 9) [activated|h_prev]@[Wz|Wr] ; sigmoid -> z (fp32), h_prev*r (fp16)
    mma_gemm<2><<<dim3(16, 32), 256, SMEM_BYTES>>>(
        acth, 2 * DOUT, 2 * DOUT, hph, DOUT,
        wzr, 3072,
        b_z, b_r, h_prev, nullptr,
        zbuf, hrh);

    // 10) n = tanh([activated|h*r]@W_n + b_n) ; h_next = (1-z)h + z n
    mma_gemm<3><<<dim3(8, 32), 256, SMEM_BYTES>>>(
        acth, 2 * DOUT, 2 * DOUT, hrh, DOUT,
        wn, 3072,
        b_n, zbuf, h_prev, nullptr,
        h_out, nullptr);
}